// round 1
// baseline (speedup 1.0000x reference)
#include <cuda_runtime.h>
#include <math.h>

// Problem constants (fixed shapes)
#define B_  2
#define H_  16
#define S_  2048
#define D_  128
#define BS_ 128
#define NB_ 16

// Per-query-block active-j lists, built by decode kernel each launch.
__device__ int g_active[NB_][NB_];
__device__ int g_count[NB_];

// ---------------------------------------------------------------------------
// Mask decode: block_mask may arrive as bool(u8), int32, or float32. Classify
// from the first 256 bytes (safe for all encodings), then build lists.
// The forced-true diagonal entry at flat index 17 guarantees a nonzero byte
// at a non-multiple-of-4 offset iff the encoding is 1-byte, making the
// u8-vs-i32 discrimination deterministic (f32's 0x80/0x3f bytes are likewise
// unambiguous vs 0/1 bool bytes).
// ---------------------------------------------------------------------------
__global__ void decode_mask_kernel(const unsigned char* __restrict__ mraw) {
    __shared__ int fmt_s;
    const int t = threadIdx.x;
    if (t == 0) {
        bool f32ok = true, i32ok = true;
        for (int g = 0; g < 64; g++) {
            unsigned char b0 = mraw[4 * g + 0], b1 = mraw[4 * g + 1];
            unsigned char b2 = mraw[4 * g + 2], b3 = mraw[4 * g + 3];
            bool zero = (b0 | b1 | b2 | b3) == 0;
            bool fone = (b0 == 0 && b1 == 0 && b2 == 0x80 && b3 == 0x3f);
            if (!(zero || fone)) f32ok = false;
            if ((b1 | b2 | b3) != 0) i32ok = false;
        }
        fmt_s = f32ok ? 2 : (i32ok ? 1 : 0);
    }
    __syncthreads();
    const int fmt = fmt_s;
    if (t < NB_) {
        int cnt = 0;
        for (int j = 0; j < NB_; j++) {
            const int idx = t * NB_ + j;
            int v;
            if (fmt == 0)      v = (mraw[idx] != 0);
            else if (fmt == 1) v = (((const int*)mraw)[idx] != 0);
            else               v = (((const float*)mraw)[idx] != 0.0f);
            if (v) g_active[t][cnt++] = j;
        }
        g_count[t] = cnt;
    }
}

// ---------------------------------------------------------------------------
// Main kernel. One CTA per (b, h, query-block i). 256 threads as 16x16 grid,
// each thread owns an 8x8 micro-tile. SMEM: Qs | KP (K tile, reused for P) |
// Vs, each 128x128 f32 with XOR swizzle: 16B-chunk index c stored at
// c ^ ((row >> 3) & 7). This makes K-frag loads (chunk varies with tx)
// conflict-free and Q/P-frag loads pure broadcast.
// ---------------------------------------------------------------------------
__global__ __launch_bounds__(256, 1)
void bs_attn_kernel(const float* __restrict__ Qg,
                    const float* __restrict__ Kg,
                    const float* __restrict__ Vg,
                    float* __restrict__ Og) {
    extern __shared__ float smem[];
    float* Qs = smem;            // 128*128
    float* KP = smem + 16384;    // K tile, then P tile
    float* Vs = smem + 32768;    // V tile

    const int i = blockIdx.x, h = blockIdx.y, b = blockIdx.z;
    const int tid = threadIdx.x;
    const int tx = tid & 15, ty = tid >> 4;
    const int q0 = ty * 8;       // rows of S / O owned by this thread
    const int c0 = tx * 8;       // cols (keys in S, dims in O)
    const int sQ = ty & 7;       // swizzle constant for rows q0..q0+7
    const int sK = tx & 7;       // swizzle constant for rows c0..c0+7

    const size_t bh = ((size_t)(b * H_ + h)) * S_ * D_;
    const float* Qrow = Qg + bh + (size_t)i * BS_ * D_;

    // Stage Q (swizzled)
    for (int idx = tid; idx < BS_ * 32; idx += 256) {
        const int r = idx >> 5, c = idx & 31;
        float4 v = __ldg((const float4*)(Qrow + (size_t)r * D_) + c);
        *(float4*)&Qs[r * 128 + ((c ^ ((r >> 3) & 7)) << 2)] = v;
    }

    float o[8][8];
#pragma unroll
    for (int u = 0; u < 8; u++)
#pragma unroll
        for (int j = 0; j < 8; j++) o[u][j] = 0.0f;

    const int cnt = g_count[i];
    const float scale = 0.08838834764831845f;  // 1/sqrt(128)

    __syncthreads();

    for (int jj = 0; jj < cnt; jj++) {
        const int jb = g_active[i][jj];
        const float* Krow = Kg + bh + (size_t)jb * BS_ * D_;
        const float* Vrow = Vg + bh + (size_t)jb * BS_ * D_;

        // Stage K and V tiles (swizzled). KP may hold last iter's P; the
        // trailing __syncthreads of the loop body ordered those reads.
        for (int idx = tid; idx < BS_ * 32; idx += 256) {
            const int r = idx >> 5, c = idx & 31;
            const int sw = ((c ^ ((r >> 3) & 7)) << 2);
            float4 kv = __ldg((const float4*)(Krow + (size_t)r * D_) + c);
            *(float4*)&KP[r * 128 + sw] = kv;
            float4 vv = __ldg((const float4*)(Vrow + (size_t)r * D_) + c);
            *(float4*)&Vs[r * 128 + sw] = vv;
        }
        __syncthreads();

        // ---- S = Q @ K^T (128x128x128), thread tile 8x8 ----
        float sacc[8][8];
#pragma unroll
        for (int u = 0; u < 8; u++)
#pragma unroll
            for (int j = 0; j < 8; j++) sacc[u][j] = 0.0f;

#pragma unroll 2
        for (int d4 = 0; d4 < 32; d4++) {
            float4 bb[8];
#pragma unroll
            for (int j = 0; j < 8; j++)
                bb[j] = *(const float4*)&KP[(c0 + j) * 128 + ((d4 ^ sK) << 2)];
#pragma unroll
            for (int u = 0; u < 8; u++) {
                float4 aa = *(const float4*)&Qs[(q0 + u) * 128 + ((d4 ^ sQ) << 2)];
#pragma unroll
                for (int j = 0; j < 8; j++) {
                    sacc[u][j] = fmaf(aa.x, bb[j].x, sacc[u][j]);
                    sacc[u][j] = fmaf(aa.y, bb[j].y, sacc[u][j]);
                    sacc[u][j] = fmaf(aa.z, bb[j].z, sacc[u][j]);
                    sacc[u][j] = fmaf(aa.w, bb[j].w, sacc[u][j]);
                }
            }
        }

        // ---- Per-row softmax; each row split across the 16 tx lanes ----
#pragma unroll
        for (int u = 0; u < 8; u++) {
            float m = -1e30f;
#pragma unroll
            for (int j = 0; j < 8; j++) {
                sacc[u][j] *= scale;
                m = fmaxf(m, sacc[u][j]);
            }
#pragma unroll
            for (int off = 8; off > 0; off >>= 1)
                m = fmaxf(m, __shfl_xor_sync(0xffffffffu, m, off, 16));
            float sum = 0.0f;
#pragma unroll
            for (int j = 0; j < 8; j++) {
                sacc[u][j] = __expf(sacc[u][j] - m);
                sum += sacc[u][j];
            }
#pragma unroll
            for (int off = 8; off > 0; off >>= 1)
                sum += __shfl_xor_sync(0xffffffffu, sum, off, 16);
            const float rinv = __fdividef(1.0f, sum);
#pragma unroll
            for (int j = 0; j < 8; j++) sacc[u][j] *= rinv;
        }

        __syncthreads();  // all K-tile reads complete before P overwrites KP

        // ---- P -> SMEM (reuse KP), rows q0.., cols c0.., swizzled ----
        {
            const int cA = c0 >> 2;  // first 16B chunk of this thread's cols
#pragma unroll
            for (int u = 0; u < 8; u++) {
                const int row = q0 + u;
                float4 p0 = make_float4(sacc[u][0], sacc[u][1], sacc[u][2], sacc[u][3]);
                float4 p1 = make_float4(sacc[u][4], sacc[u][5], sacc[u][6], sacc[u][7]);
                *(float4*)&KP[row * 128 + ((cA ^ sQ) << 2)] = p0;
                *(float4*)&KP[row * 128 + (((cA + 1) ^ sQ) << 2)] = p1;
            }
        }
        __syncthreads();

        // ---- O += P @ V (128x128x128) ----
#pragma unroll 2
        for (int k4 = 0; k4 < 32; k4++) {
            float4 v0[4], v1[4];
#pragma unroll
            for (int w = 0; w < 4; w++) {
                const int vr = k4 * 4 + w;
                const int svz = (vr >> 3) & 7;
                v0[w] = *(const float4*)&Vs[vr * 128 + (((tx * 2) ^ svz) << 2)];
                v1[w] = *(const float4*)&Vs[vr * 128 + (((tx * 2 + 1) ^ svz) << 2)];
            }
#pragma unroll
            for (int u = 0; u < 8; u++) {
                float4 pa = *(const float4*)&KP[(q0 + u) * 128 + ((k4 ^ sQ) << 2)];
#pragma unroll
                for (int w = 0; w < 4; w++) {
                    const float p = (w == 0) ? pa.x : (w == 1) ? pa.y : (w == 2) ? pa.z : pa.w;
                    o[u][0] = fmaf(p, v0[w].x, o[u][0]);
                    o[u][1] = fmaf(p, v0[w].y, o[u][1]);
                    o[u][2] = fmaf(p, v0[w].z, o[u][2]);
                    o[u][3] = fmaf(p, v0[w].w, o[u][3]);
                    o[u][4] = fmaf(p, v1[w].x, o[u][4]);
                    o[u][5] = fmaf(p, v1[w].y, o[u][5]);
                    o[u][6] = fmaf(p, v1[w].z, o[u][6]);
                    o[u][7] = fmaf(p, v1[w].w, o[u][7]);
                }
            }
        }
        __syncthreads();  // P/V reads done before next iteration restages
    }

    // ---- Write O ----
    float* Orow = Og + bh + (size_t)i * BS_ * D_;
#pragma unroll
    for (int u = 0; u < 8; u++) {
        float4 w0 = make_float4(o[u][0], o[u][1], o[u][2], o[u][3]);
        float4 w1 = make_float4(o[u][4], o[u][5], o[u][6], o[u][7]);
        *(float4*)&Orow[(size_t)(q0 + u) * D_ + c0] = w0;
        *(float4*)&Orow[(size_t)(q0 + u) * D_ + c0 + 4] = w1;
    }
}

// ---------------------------------------------------------------------------
extern "C" void kernel_launch(void* const* d_in, const int* in_sizes, int n_in,
                              void* d_out, int out_size) {
    const float* Q = (const float*)d_in[0];
    const float* K = (const float*)d_in[1];
    const float* V = (const float*)d_in[2];

    // block_mask is the NB*NB=256-element input among the trailing args
    int mask_idx = 3;
    for (int t = 3; t < n_in; t++) {
        if (in_sizes[t] == NB_ * NB_) { mask_idx = t; break; }
    }
    const unsigned char* M = (const unsigned char*)d_in[mask_idx];
    float* O = (float*)d_out;

    decode_mask_kernel<<<1, 32>>>(M);

    const int smem_bytes = 3 * 128 * 128 * (int)sizeof(float);  // 196608
    cudaFuncSetAttribute(bs_attn_kernel,
                         cudaFuncAttributeMaxDynamicSharedMemorySize, smem_bytes);
    dim3 grid(NB_, H_, B_);
    bs_attn_kernel<<<grid, 256, smem_bytes>>>(Q, K, V, O);
}

// round 3
// speedup vs baseline: 1.9920x; 1.9920x over previous
#include <cuda_runtime.h>
#include <cuda_bf16.h>
#include <stdint.h>

#define B_  2
#define H_  16
#define S_  2048
#define D_  128
#define BS_ 128
#define NB_ 16
#define NTILE (B_*H_*NB_)   // 512 tiles of 128 rows

__device__ int g_active[NB_][NB_];
__device__ int g_count[NB_];
// Pre-split, pre-swizzled bf16 tiles (32KB each): [tile][2048 uint4]
__device__ uint4 g_khi[NTILE * 2048];
__device__ uint4 g_klo[NTILE * 2048];
__device__ uint4 g_vhi[NTILE * 2048];
__device__ uint4 g_vlo[NTILE * 2048];

// ---------------- helpers ----------------
__device__ __forceinline__ uint32_t smem_u32(const void* p) {
    uint32_t a;
    asm("{ .reg .u64 t; cvta.to.shared.u64 t, %1; cvt.u32.u64 %0, t; }" : "=r"(a) : "l"(p));
    return a;
}
__device__ __forceinline__ void cpa16(uint32_t dst, const void* src) {
    asm volatile("cp.async.cg.shared.global [%0], [%1], 16;" :: "r"(dst), "l"(src));
}
__device__ __forceinline__ void ldsm_x4(uint32_t addr, uint32_t r[4]) {
    asm volatile("ldmatrix.sync.aligned.m8n8.x4.shared.b16 {%0,%1,%2,%3}, [%4];"
        : "=r"(r[0]), "=r"(r[1]), "=r"(r[2]), "=r"(r[3]) : "r"(addr));
}
__device__ __forceinline__ void ldsm_x4_t(uint32_t addr, uint32_t r[4]) {
    asm volatile("ldmatrix.sync.aligned.m8n8.x4.trans.shared.b16 {%0,%1,%2,%3}, [%4];"
        : "=r"(r[0]), "=r"(r[1]), "=r"(r[2]), "=r"(r[3]) : "r"(addr));
}
__device__ __forceinline__ void mma_bf16(float c[4], const uint32_t a[4],
                                         uint32_t b0, uint32_t b1) {
    asm volatile("mma.sync.aligned.m16n8k16.row.col.f32.bf16.bf16.f32 "
        "{%0,%1,%2,%3}, {%4,%5,%6,%7}, {%8,%9}, {%0,%1,%2,%3};"
        : "+f"(c[0]), "+f"(c[1]), "+f"(c[2]), "+f"(c[3])
        : "r"(a[0]), "r"(a[1]), "r"(a[2]), "r"(a[3]), "r"(b0), "r"(b1));
}
// split x into bf16 hi + bf16 lo (x ~= hi + lo), packed two at a time
__device__ __forceinline__ void split2(float x, float y, uint32_t& hi, uint32_t& lo) {
    __nv_bfloat162 h = __float22bfloat162_rn(make_float2(x, y));
    float2 rr = make_float2(x - __bfloat162float(h.x), y - __bfloat162float(h.y));
    __nv_bfloat162 l = __float22bfloat162_rn(rr);
    hi = *(uint32_t*)&h;
    lo = *(uint32_t*)&l;
}
__device__ __forceinline__ void split8(const float* v, uint4& hi, uint4& lo) {
    uint32_t hw[4], lw[4];
#pragma unroll
    for (int j = 0; j < 4; ++j) split2(v[2*j], v[2*j+1], hw[j], lw[j]);
    hi = make_uint4(hw[0], hw[1], hw[2], hw[3]);
    lo = make_uint4(lw[0], lw[1], lw[2], lw[3]);
}

// ---------------- mask decode ----------------
__global__ void decode_mask_kernel(const unsigned char* __restrict__ mraw) {
    __shared__ int fmt_s;
    const int t = threadIdx.x;
    if (t == 0) {
        bool f32ok = true, i32ok = true;
        for (int g = 0; g < 64; g++) {
            unsigned char b0 = mraw[4*g+0], b1 = mraw[4*g+1];
            unsigned char b2 = mraw[4*g+2], b3 = mraw[4*g+3];
            bool zero = (b0 | b1 | b2 | b3) == 0;
            bool fone = (b0 == 0 && b1 == 0 && b2 == 0x80 && b3 == 0x3f);
            if (!(zero || fone)) f32ok = false;
            if ((b1 | b2 | b3) != 0) i32ok = false;
        }
        fmt_s = f32ok ? 2 : (i32ok ? 1 : 0);
    }
    __syncthreads();
    const int fmt = fmt_s;
    if (t < NB_) {
        int cnt = 0;
        for (int j = 0; j < NB_; j++) {
            const int idx = t * NB_ + j;
            int v;
            if (fmt == 0)      v = (mraw[idx] != 0);
            else if (fmt == 1) v = (((const int*)mraw)[idx] != 0);
            else               v = (((const float*)mraw)[idx] != 0.0f);
            if (v) g_active[t][cnt++] = j;
        }
        g_count[t] = cnt;
    }
}

// ---------------- K/V prepass: split-bf16 + swizzled tile image ----------------
__global__ __launch_bounds__(256, 1)
void prep_kv(const float* __restrict__ Kg, const float* __restrict__ Vg) {
    const int t = blockIdx.x;   // 0..1023 : first 512 = K tiles, next 512 = V tiles
    const bool isK = (t < NTILE);
    const int tt = isK ? t : (t - NTILE);
    const float* src = (isK ? Kg : Vg) + (size_t)tt * BS_ * D_;
    uint4* dh = (isK ? g_khi : g_vhi) + (size_t)tt * 2048;
    uint4* dl = (isK ? g_klo : g_vlo) + (size_t)tt * 2048;
    const int tid = threadIdx.x;
#pragma unroll
    for (int it = 0; it < 8; ++it) {
        const int idx = it * 256 + tid;          // 2048 chunks
        const int r = idx >> 4, c = idx & 15;    // row, 16B chunk
        const float4 a = __ldg((const float4*)(src + (size_t)r * D_ + c * 8));
        const float4 b = __ldg((const float4*)(src + (size_t)r * D_ + c * 8) + 1);
        float v[8] = {a.x, a.y, a.z, a.w, b.x, b.y, b.z, b.w};
        uint4 hi, lo; split8(v, hi, lo);
        const int o = r * 16 + (c ^ (r & 7));    // swizzled chunk index
        dh[o] = hi; dl[o] = lo;
    }
}

// ---------------- main attention kernel ----------------
// SMEM: six 32KB bf16 tiles (128 rows x 256B, XOR-swizzled 16B chunks)
#define QHI 0u
#define QLO 32768u
#define KHI 65536u
#define KLO 98304u
#define VHI 131072u
#define VLO 163840u
#define SMEM_NEED (196608u + 1024u)

__global__ __launch_bounds__(256, 1)
void attn_main(const float* __restrict__ Qg, float* __restrict__ Og) {
    extern __shared__ char dsm[];
    char* smem = (char*)(((uintptr_t)dsm + 1023) & ~(uintptr_t)1023);
    const uint32_t sb = smem_u32(smem);

    const int i = blockIdx.x, h = blockIdx.y, b = blockIdx.z;
    const int tid = threadIdx.x, wid = tid >> 5, lane = tid & 31;
    const size_t bh = ((size_t)(b * H_ + h)) * S_ * D_;
    const int tbase = (b * H_ + h) * NB_;

    // ---- stage Q once (scale folded), split + swizzled ----
    const float scale = 0.08838834764831845f;
    const float* Qrow = Qg + bh + (size_t)i * BS_ * D_;
#pragma unroll
    for (int it = 0; it < 8; ++it) {
        const int idx = it * 256 + tid;
        const int r = idx >> 4, c = idx & 15;
        const float4 a = __ldg((const float4*)(Qrow + (size_t)r * D_ + c * 8));
        const float4 bb = __ldg((const float4*)(Qrow + (size_t)r * D_ + c * 8) + 1);
        float v[8] = {a.x*scale, a.y*scale, a.z*scale, a.w*scale,
                      bb.x*scale, bb.y*scale, bb.z*scale, bb.w*scale};
        uint4 hi, lo; split8(v, hi, lo);
        const uint32_t o = (uint32_t)(r * 256 + ((c ^ (r & 7)) << 4));
        *(uint4*)(smem + QHI + o) = hi;
        *(uint4*)(smem + QLO + o) = lo;
    }

    // ldmatrix lane-address constants
    const int m0 = wid * 16;
    const int r8 = lane & 7, sel = lane >> 3;
    // A-type (rows = m): matrices {m0..+7,k0}, {m0+8..,k0}, {m0..,k0+8}, {m0+8..,k0+8}
    const int a_row = m0 + r8 + ((sel & 1) << 3);
    const uint32_t a_rowoff = (uint32_t)a_row * 256;
    const int a_swz = a_row & 7, a_cs = sel >> 1;
    // B-K type (rows = n): row = n0 + r8 + (sel>>1)*8 ; chunk = k0/8 + (sel&1)
    const int bk_radd = r8 + ((sel >> 1) << 3);
    const int bk_cs = sel & 1;
    // B-V type (rows = k): row = k0 + r8 + (sel&1)*8 ; chunk = n0/8 + (sel>>1)
    const int bv_radd = r8 + ((sel & 1) << 3);
    const int bv_cs = sel >> 1;

    float oacc[16][4];
#pragma unroll
    for (int t = 0; t < 16; ++t)
#pragma unroll
        for (int j = 0; j < 4; ++j) oacc[t][j] = 0.0f;

    const int cnt = g_count[i];
    __syncthreads();

    for (int jj = 0; jj < cnt; ++jj) {
        const int jb = g_active[i][jj];
        const size_t tile = (size_t)(tbase + jb) * 2048;
        if (jj > 0) __syncthreads();   // prior pair done reading K/V

        // ---- stage K,V (pure cp.async of pre-swizzled images) ----
        const uint4* skh = g_khi + tile; const uint4* skl = g_klo + tile;
        const uint4* svh = g_vhi + tile; const uint4* svl = g_vlo + tile;
#pragma unroll
        for (int it = 0; it < 8; ++it) {
            const int idx = it * 256 + tid;
            cpa16(sb + KHI + idx * 16, skh + idx);
            cpa16(sb + KLO + idx * 16, skl + idx);
            cpa16(sb + VHI + idx * 16, svh + idx);
            cpa16(sb + VLO + idx * 16, svl + idx);
        }
        asm volatile("cp.async.commit_group;\n\tcp.async.wait_group 0;" ::: "memory");
        __syncthreads();

        // ---- S = Q K^T, split-bf16 3 terms; warp owns 16 rows x 128 cols ----
        float sacc[16][4];
#pragma unroll
        for (int t = 0; t < 16; ++t)
#pragma unroll
            for (int j = 0; j < 4; ++j) sacc[t][j] = 0.0f;

#pragma unroll
        for (int ks = 0; ks < 8; ++ks) {
            uint32_t ah[4], al[4];
            const uint32_t ac = a_rowoff + (uint32_t)((((2*ks + a_cs) ^ a_swz)) << 4);
            ldsm_x4(sb + QHI + ac, ah);
            ldsm_x4(sb + QLO + ac, al);
#pragma unroll
            for (int nt2 = 0; nt2 < 8; ++nt2) {
                const int brow = nt2 * 16 + bk_radd;
                const uint32_t boff = (uint32_t)(brow * 256 +
                                     (((2*ks + bk_cs) ^ (brow & 7)) << 4));
                uint32_t bhh[4], bll[4];
                ldsm_x4(sb + KHI + boff, bhh);
                ldsm_x4(sb + KLO + boff, bll);
                mma_bf16(sacc[2*nt2],   ah, bhh[0], bhh[1]);
                mma_bf16(sacc[2*nt2],   ah, bll[0], bll[1]);
                mma_bf16(sacc[2*nt2],   al, bhh[0], bhh[1]);
                mma_bf16(sacc[2*nt2+1], ah, bhh[2], bhh[3]);
                mma_bf16(sacc[2*nt2+1], ah, bll[2], bll[3]);
                mma_bf16(sacc[2*nt2+1], al, bhh[2], bhh[3]);
            }
        }

        // ---- per-row softmax (rows fully within warp; quad reduction) ----
        float mx0 = -1e30f, mx1 = -1e30f;
#pragma unroll
        for (int t = 0; t < 16; ++t) {
            mx0 = fmaxf(mx0, fmaxf(sacc[t][0], sacc[t][1]));
            mx1 = fmaxf(mx1, fmaxf(sacc[t][2], sacc[t][3]));
        }
        mx0 = fmaxf(mx0, __shfl_xor_sync(0xffffffffu, mx0, 1));
        mx0 = fmaxf(mx0, __shfl_xor_sync(0xffffffffu, mx0, 2));
        mx1 = fmaxf(mx1, __shfl_xor_sync(0xffffffffu, mx1, 1));
        mx1 = fmaxf(mx1, __shfl_xor_sync(0xffffffffu, mx1, 2));
        float s0 = 0.0f, s1 = 0.0f;
#pragma unroll
        for (int t = 0; t < 16; ++t) {
            sacc[t][0] = __expf(sacc[t][0] - mx0); s0 += sacc[t][0];
            sacc[t][1] = __expf(sacc[t][1] - mx0); s0 += sacc[t][1];
            sacc[t][2] = __expf(sacc[t][2] - mx1); s1 += sacc[t][2];
            sacc[t][3] = __expf(sacc[t][3] - mx1); s1 += sacc[t][3];
        }
        s0 += __shfl_xor_sync(0xffffffffu, s0, 1);
        s0 += __shfl_xor_sync(0xffffffffu, s0, 2);
        s1 += __shfl_xor_sync(0xffffffffu, s1, 1);
        s1 += __shfl_xor_sync(0xffffffffu, s1, 2);
        const float inv0 = __fdividef(1.0f, s0);
        const float inv1 = __fdividef(1.0f, s1);

        // ---- O += P V ; P converted in-register (C-frag -> A-frag layout) ----
#pragma unroll
        for (int g = 0; g < 8; ++g) {
            uint32_t pah[4], pal[4];
            split2(sacc[2*g][0]*inv0,   sacc[2*g][1]*inv0,   pah[0], pal[0]);
            split2(sacc[2*g][2]*inv1,   sacc[2*g][3]*inv1,   pah[1], pal[1]);
            split2(sacc[2*g+1][0]*inv0, sacc[2*g+1][1]*inv0, pah[2], pal[2]);
            split2(sacc[2*g+1][2]*inv1, sacc[2*g+1][3]*inv1, pah[3], pal[3]);
            const int vrow = g * 16 + bv_radd;
            const uint32_t vro = (uint32_t)(vrow * 256);
            const int vswz = vrow & 7;
#pragma unroll
            for (int nt2 = 0; nt2 < 8; ++nt2) {
                const uint32_t voff = vro + (uint32_t)((((2*nt2 + bv_cs) ^ vswz)) << 4);
                uint32_t bhh[4], bll[4];
                ldsm_x4_t(sb + VHI + voff, bhh);
                ldsm_x4_t(sb + VLO + voff, bll);
                mma_bf16(oacc[2*nt2],   pah, bhh[0], bhh[1]);
                mma_bf16(oacc[2*nt2],   pah, bll[0], bll[1]);
                mma_bf16(oacc[2*nt2],   pal, bhh[0], bhh[1]);
                mma_bf16(oacc[2*nt2+1], pah, bhh[2], bhh[3]);
                mma_bf16(oacc[2*nt2+1], pah, bll[2], bll[3]);
                mma_bf16(oacc[2*nt2+1], pal, bhh[2], bhh[3]);
            }
        }
    }

    // ---- write O ----
    float* Ob = Og + bh + (size_t)i * BS_ * D_;
    const int row0 = m0 + (lane >> 2);
    const int colb = 2 * (lane & 3);
#pragma unroll
    for (int nt = 0; nt < 16; ++nt) {
        const int col = nt * 8 + colb;
        *(float2*)&Ob[(size_t)row0 * D_ + col]       = make_float2(oacc[nt][0], oacc[nt][1]);
        *(float2*)&Ob[(size_t)(row0 + 8) * D_ + col] = make_float2(oacc[nt][2], oacc[nt][3]);
    }
}

// ---------------- launch ----------------
extern "C" void kernel_launch(void* const* d_in, const int* in_sizes, int n_in,
                              void* d_out, int out_size) {
    const float* Q = (const float*)d_in[0];
    const float* K = (const float*)d_in[1];
    const float* V = (const float*)d_in[2];
    int mask_idx = 3;
    for (int t = 3; t < n_in; t++)
        if (in_sizes[t] == NB_ * NB_) { mask_idx = t; break; }
    const unsigned char* M = (const unsigned char*)d_in[mask_idx];
    float* O = (float*)d_out;

    decode_mask_kernel<<<1, 32>>>(M);
    prep_kv<<<2 * NTILE, 256>>>(K, V);

    cudaFuncSetAttribute(attn_main, cudaFuncAttributeMaxDynamicSharedMemorySize, SMEM_NEED);
    dim3 grid(NB_, H_, B_);
    attn_main<<<grid, 256, SMEM_NEED>>>(Q, O);
}